// round 15
// baseline (speedup 1.0000x reference)
#include <cuda_runtime.h>
#include <cuda_bf16.h>
#include <cstdint>
#include <cstddef>

// ---------------- problem maxima: 12800 ref, 25600 in, 256 feat, 64 props ----
#define NREF_MAX 16384
#define NIN_MAX  32768
#define NP_MAX   64
#define MAXG     16
#define BC       128     // input-atom columns per tile
#define RC       64      // ref atoms per chunk
#define KS       32      // feature K-slice per pipeline stage
#define NTILE_MAX 512
#define NSPLIT   4       // ref-chunk split per tile (work units = tiles * NSPLIT)
#define GRID_MAIN 296    // persistent CTAs (148 SMs x 2)

// ---------------- device scratch (static: no allocation) ----------------
__device__ int d_ng, d_nt, d_totref, d_totin;
__device__ int d_wctr;
__device__ int d_gref_off[MAXG], d_gref_cnt[MAXG];
__device__ int d_gin_off[MAXG],  d_gin_cnt[MAXG];
__device__ int d_tile_g[NTILE_MAX], d_tile_c0[NTILE_MAX];
// tile completion counters: static zero-init; last arriver resets to 0 -> replay-safe.
__device__ int d_tile_done[NTILE_MAX];
// perm arrays: static zero-init; gap entries never written -> deterministic.
__device__ int d_ref_perm[NREF_MAX], d_in_perm[NIN_MAX];
__device__ __nv_bfloat16 d_Xrh[(size_t)NREF_MAX * 256];
__device__ __nv_bfloat16 d_Xrl[(size_t)NREF_MAX * 256];
__device__ __nv_bfloat16 d_Xih[(size_t)NIN_MAX  * 256];
__device__ __nv_bfloat16 d_Xil[(size_t)NIN_MAX  * 256];
__device__ __nv_bfloat16 d_Ath[(size_t)NP_MAX * NREF_MAX]; // [prop][ref_grouped]
__device__ __nv_bfloat16 d_Atl[(size_t)NP_MAX * NREF_MAX];
// fragment-ready At: [rblk(256)][ks(4)][q(4)][half(2)][lane(32)] x uint4
__device__ uint4 d_AtF[262144];
// d_part: static zero-init; covered entries rewritten every launch; per-column
// ownership is unique (each column belongs to exactly one tile) -> deterministic.
__device__ float d_part[(size_t)NSPLIT * NP_MAX * NIN_MAX];

// ---------------- helpers ----------------
__device__ __forceinline__ uint32_t smem_u32(const void* p) {
    uint32_t a;
    asm("{ .reg .u64 t; cvta.to.shared.u64 t, %1; cvt.u32.u64 %0, t; }" : "=r"(a) : "l"(p));
    return a;
}
#define LDSM_X4(r0, r1, r2, r3, addr) \
    asm volatile("ldmatrix.sync.aligned.m8n8.x4.shared.b16 {%0,%1,%2,%3}, [%4];" \
        : "=r"(r0), "=r"(r1), "=r"(r2), "=r"(r3) : "r"(addr))
#define MMA_BF16(c, a, b0, b1) \
    asm volatile("mma.sync.aligned.m16n8k16.row.col.f32.bf16.bf16.f32 " \
        "{%0,%1,%2,%3},{%4,%5,%6,%7},{%8,%9},{%0,%1,%2,%3};" \
        : "+f"((c)[0]), "+f"((c)[1]), "+f"((c)[2]), "+f"((c)[3]) \
        : "r"((a)[0]), "r"((a)[1]), "r"((a)[2]), "r"((a)[3]), "r"(b0), "r"(b1))
#define CP_ASYNC16(sa, ga, ssz) \
    asm volatile("cp.async.cg.shared.global [%0], [%1], 16, %2;" \
        :: "r"(sa), "l"(ga), "r"(ssz) : "memory")
#define CP_COMMIT() asm volatile("cp.async.commit_group;" ::: "memory")
#define CP_WAIT1()  asm volatile("cp.async.wait_group 1;" ::: "memory")
#define CP_WAIT0()  asm volatile("cp.async.wait_group 0;" ::: "memory")

__device__ __forceinline__ uint32_t pack_bf16(float lo, float hi) {
    uint32_t d;
    asm("cvt.rn.bf16x2.f32 %0, %1, %2;" : "=r"(d) : "f"(hi), "f"(lo));
    return d;
}
__device__ __forceinline__ float ipow_f(float x, int e) {
    if (e == 2) return x * x;
    if (e == 1) return x;
    float r = 1.0f, b = x; int k = e;
    while (k > 0) { if (k & 1) r *= b; b *= b; k >>= 1; }
    return r;
}

// ---- smem: 3-stage pipeline, Xi/Xr only. pitch 80B rows (32 bf16 + 16B pad) ----
#define PX      80
#define XI_HB   (128 * PX)                 // 10240 per (stage,half)
#define XR_HB   (64 * PX)                  // 5120
#define OFF_XI  0
#define OFF_XR  (OFF_XI + 6 * XI_HB)       // 61440
#define SMEM_TOTAL (OFF_XR + 6 * XR_HB)    // 92160 (proven envelope)

// ---------------- prep: dtype-detect Z, histogram, aligned groups, perm ----------
__global__ void prep_kernel(const int* __restrict__ Zr, const int* __restrict__ Zi,
                            int Nref, int Nin) {
    __shared__ int s_h_ref[256], s_h_in[256], s_gmap[256];
    __shared__ int s_flag[2];
    __shared__ int s_lcs[256][MAXG];
    int tid = threadIdx.x;

    if (tid < 2) s_flag[tid] = 1;
    for (int v = tid; v < 256; v += 256) { s_h_ref[v] = 0; s_h_in[v] = 0; s_gmap[v] = -1; }
    __syncthreads();

    for (int i = 1 + 2 * tid; i < Nref; i += 512) if (Zr[i] != 0) { s_flag[0] = 0; break; }
    for (int i = 1 + 2 * tid; i < Nin;  i += 512) if (Zi[i] != 0) { s_flag[1] = 0; break; }
    __syncthreads();
    const int r64 = s_flag[0], i64 = s_flag[1];

    for (int i = tid; i < Nref; i += 256) {
        int v = Zr[r64 ? 2 * i : i];
        if (v >= 1 && v < 256) atomicAdd(&s_h_ref[v], 1);
    }
    for (int i = tid; i < Nin; i += 256) {
        int v = Zi[i64 ? 2 * i : i];
        if (v >= 1 && v < 256) atomicAdd(&s_h_in[v], 1);
    }
    __syncthreads();

    if (tid == 0) {
        int ng = 0, roff = 0, ioff = 0, nt = 0;
        for (int v = 1; v < 256; v++) {
            if (s_h_in[v] > 0 && ng < MAXG) {
                roff = (roff + 63) & ~63; ioff = (ioff + 63) & ~63;
                s_gmap[v] = ng;
                d_gref_off[ng] = roff; d_gref_cnt[ng] = s_h_ref[v];
                d_gin_off[ng]  = ioff; d_gin_cnt[ng]  = s_h_in[v];
                for (int c0 = 0; c0 < s_h_in[v]; c0 += BC)
                    if (nt < NTILE_MAX) { d_tile_g[nt] = ng; d_tile_c0[nt] = c0; nt++; }
                roff += s_h_ref[v]; ioff += s_h_in[v]; ng++;
            }
        }
        d_ng = ng; d_nt = nt; d_totref = roff; d_totin = ioff;
        d_wctr = 0;
    }
    __syncthreads();
    const int ng = d_ng;

    { // counting-sort perm: ref
        int chunk = (Nref + 255) >> 8;
        int i0 = tid * chunk, i1 = min(Nref, i0 + chunk);
        int lc[MAXG];
        #pragma unroll
        for (int g = 0; g < MAXG; g++) lc[g] = 0;
        for (int i = i0; i < i1; i++) {
            int v = Zr[r64 ? 2 * i : i];
            int g = (v >= 1 && v < 256) ? s_gmap[v] : -1;
            if (g >= 0) lc[g]++;
        }
        #pragma unroll
        for (int g = 0; g < MAXG; g++) s_lcs[tid][g] = lc[g];
        __syncthreads();
        if (tid < ng) {
            int acc = d_gref_off[tid];
            for (int t = 0; t < 256; t++) { int x = s_lcs[t][tid]; s_lcs[t][tid] = acc; acc += x; }
        }
        __syncthreads();
        int cur[MAXG];
        #pragma unroll
        for (int g = 0; g < MAXG; g++) cur[g] = s_lcs[tid][g];
        for (int i = i0; i < i1; i++) {
            int v = Zr[r64 ? 2 * i : i];
            int g = (v >= 1 && v < 256) ? s_gmap[v] : -1;
            if (g >= 0) { int p = cur[g]++; if (p < NREF_MAX) d_ref_perm[p] = i; }
        }
        __syncthreads();
    }
    { // counting-sort perm: input
        int chunk = (Nin + 255) >> 8;
        int i0 = tid * chunk, i1 = min(Nin, i0 + chunk);
        int lc[MAXG];
        #pragma unroll
        for (int g = 0; g < MAXG; g++) lc[g] = 0;
        for (int i = i0; i < i1; i++) {
            int v = Zi[i64 ? 2 * i : i];
            int g = (v >= 1 && v < 256) ? s_gmap[v] : -1;
            if (g >= 0) lc[g]++;
        }
        #pragma unroll
        for (int g = 0; g < MAXG; g++) s_lcs[tid][g] = lc[g];
        __syncthreads();
        if (tid < ng) {
            int acc = d_gin_off[tid];
            for (int t = 0; t < 256; t++) { int x = s_lcs[t][tid]; s_lcs[t][tid] = acc; acc += x; }
        }
        __syncthreads();
        int cur[MAXG];
        #pragma unroll
        for (int g = 0; g < MAXG; g++) cur[g] = s_lcs[tid][g];
        for (int i = i0; i < i1; i++) {
            int v = Zi[i64 ? 2 * i : i];
            int g = (v >= 1 && v < 256) ? s_gmap[v] : -1;
            if (g >= 0) { int p = cur[g]++; if (p < NIN_MAX) d_in_perm[p] = i; }
        }
    }
}

// ---------------- gather + bf16 hi/lo split (4 rows/block, vectorized) ----------
__global__ void gather_kernel(const float* __restrict__ Alpha,
                              const float* __restrict__ desc_ref,
                              const float* __restrict__ desc,
                              int np, int dfeat, int Nref, int Nin, int padRef) {
    const int tid = threadIdx.x;
    const int rl  = tid >> 6;
    const int ln  = tid & 63;
    const int row = blockIdx.x * 4 + rl;
    const bool vec = ((dfeat & 3) == 0);

    if (row < padRef) {
        if (row < d_totref) {
            int src = d_ref_perm[row];
            if (vec) {
                for (int k4 = ln * 4; k4 < dfeat; k4 += 256) {
                    float4 x = *(const float4*)&desc_ref[(size_t)src * dfeat + k4];
                    float h0 = __bfloat162float(__float2bfloat16(x.x));
                    float h1 = __bfloat162float(__float2bfloat16(x.y));
                    float h2 = __bfloat162float(__float2bfloat16(x.z));
                    float h3 = __bfloat162float(__float2bfloat16(x.w));
                    uint2 hv, lv;
                    hv.x = pack_bf16(h0, h1); hv.y = pack_bf16(h2, h3);
                    lv.x = pack_bf16(x.x - h0, x.y - h1); lv.y = pack_bf16(x.z - h2, x.w - h3);
                    *(uint2*)&d_Xrh[(size_t)row * dfeat + k4] = hv;
                    *(uint2*)&d_Xrl[(size_t)row * dfeat + k4] = lv;
                }
            } else {
                for (int k = ln; k < dfeat; k += 64) {
                    float x = desc_ref[(size_t)src * dfeat + k];
                    __nv_bfloat16 h = __float2bfloat16(x);
                    d_Xrh[(size_t)row * dfeat + k] = h;
                    d_Xrl[(size_t)row * dfeat + k] = __float2bfloat16(x - __bfloat162float(h));
                }
            }
            float a = (ln < np) ? Alpha[(size_t)ln * Nref + src] : 0.0f;
            __nv_bfloat16 h = __float2bfloat16(a);
            d_Ath[(size_t)ln * NREF_MAX + row] = h;
            d_Atl[(size_t)ln * NREF_MAX + row] = __float2bfloat16(a - __bfloat162float(h));
        }
    } else {
        int ir = row - padRef;
        if (ir < d_totin) {
            int src = d_in_perm[ir];
            if (vec) {
                for (int k4 = ln * 4; k4 < dfeat; k4 += 256) {
                    float4 x = *(const float4*)&desc[(size_t)src * dfeat + k4];
                    float h0 = __bfloat162float(__float2bfloat16(x.x));
                    float h1 = __bfloat162float(__float2bfloat16(x.y));
                    float h2 = __bfloat162float(__float2bfloat16(x.z));
                    float h3 = __bfloat162float(__float2bfloat16(x.w));
                    uint2 hv, lv;
                    hv.x = pack_bf16(h0, h1); hv.y = pack_bf16(h2, h3);
                    lv.x = pack_bf16(x.x - h0, x.y - h1); lv.y = pack_bf16(x.z - h2, x.w - h3);
                    *(uint2*)&d_Xih[(size_t)ir * dfeat + k4] = hv;
                    *(uint2*)&d_Xil[(size_t)ir * dfeat + k4] = lv;
                }
            } else {
                for (int k = ln; k < dfeat; k += 64) {
                    float x = desc[(size_t)src * dfeat + k];
                    __nv_bfloat16 h = __float2bfloat16(x);
                    d_Xih[(size_t)ir * dfeat + k] = h;
                    d_Xil[(size_t)ir * dfeat + k] = __float2bfloat16(x - __bfloat162float(h));
                }
            }
        }
    }
}

// ---------------- build fragment-ready At (coalesced via smem tile) -------------
__global__ void atfrag_kernel(int np) {
    __shared__ __align__(16) unsigned short s_at[2][64][72];
    __shared__ int s_off[MAXG], s_cnt[MAXG], s_ng;
    const int tid  = threadIdx.x;
    const int rblk = blockIdx.x;

    if (tid == 0) s_ng = d_ng;
    if (tid < MAXG) { s_off[tid] = d_gref_off[tid]; s_cnt[tid] = d_gref_cnt[tid]; }

    #pragma unroll
    for (int h = 0; h < 2; h++) {
        const __nv_bfloat16* src = h ? d_Atl : d_Ath;
        #pragma unroll
        for (int it = 0; it < 2; it++) {
            int i   = tid + it * 256;
            int row = i >> 3;
            int c   = i & 7;
            uint4 v = *(const uint4*)(src + (size_t)row * NREF_MAX + rblk * 64 + c * 8);
            *(uint4*)&s_at[h][row][c * 8] = v;
        }
    }
    __syncthreads();

    const int ng = s_ng;
    const int base_ref = rblk * 64;

    #pragma unroll
    for (int o = 0; o < 4; o++) {
        int local = tid + o * 256;
        int lid  = local & 31;
        int rest = local >> 5;
        int half = rest & 1; rest >>= 1;
        int q    = rest & 3; rest >>= 2;
        int ks   = rest & 3;
        uint32_t regs[4];
        #pragma unroll
        for (int r = 0; r < 4; r++) {
            int prop = 16 * q + 8 * (r >> 1) + (lid >> 2);
            int refl = ks * 16 + 8 * (r & 1) + 2 * (lid & 3);
            uint32_t w = *(const uint32_t*)&s_at[half][prop][refl];
            #pragma unroll
            for (int e = 0; e < 2; e++) {
                int rr = base_ref + refl + e;
                bool ing = false;
                for (int g = 0; g < ng; g++)
                    if (rr >= s_off[g] && rr < s_off[g] + s_cnt[g]) { ing = true; break; }
                if (!ing) w &= (e == 0) ? 0xFFFF0000u : 0x0000FFFFu;
            }
            regs[r] = w;
        }
        d_AtF[(size_t)rblk * 1024 + local] = make_uint4(regs[0], regs[1], regs[2], regs[3]);
    }
}

// ---------------- zero the output (uncovered columns must be 0) ----------------
__global__ void zero_out_kernel(float* __restrict__ out, size_t n) {
    for (size_t i = (size_t)blockIdx.x * blockDim.x + threadIdx.x; i < n;
         i += (size_t)gridDim.x * blockDim.x) out[i] = 0.0f;
}

// ---------------- main: persistent pipeline + fused tile-completion reduce ------
__global__ __launch_bounds__(256, 2)
void main_kernel(float* __restrict__ out, int np, int dfeat, int Nin,
                 const int* __restrict__ expKp) {
    extern __shared__ char smem[];
    __shared__ int s_unit, s_done;
    const uint32_t sb = smem_u32(smem);
    const int tid = threadIdx.x;
    const int wid = tid >> 5;
    const int lid = tid & 31;

    int ek = expKp[0];
    if (ek < 1 || ek > 64) {
        float f = __int_as_float(ek); int t = (int)f;
        ek = (t >= 1 && t <= 64) ? t : 2;
    }

    const int kcN = (dfeat + KS - 1) / KS;
    const int wrow = wid * 16;

    const uint32_t a_row  = (uint32_t)(wrow + (lid & 15));
    const uint32_t a_cofs = (uint32_t)((lid >> 4) * 16);
    const uint32_t b_rsub = (uint32_t)(8 * (lid >> 4) + (lid & 7));
    const uint32_t b_cofs = (uint32_t)(((lid >> 3) & 1) * 16);

    for (;;) {
        __syncthreads();                      // unit boundary: buffers quiesced
        if (tid == 0) s_unit = atomicAdd(&d_wctr, 1);
        __syncthreads();
        const int u = s_unit;
        const int nunits = d_nt * NSPLIT;
        if (u >= nunits) break;

        const int tile  = u >> 2;
        const int split = u & 3;
        const int g       = d_tile_g[tile];
        const int tile_c0 = d_tile_c0[tile];
        const int in_off  = d_gin_off[g];
        const int cw      = min(BC, d_gin_cnt[g] - tile_c0);
        const int roff    = d_gref_off[g];
        const int rcnt    = d_gref_cnt[g];
        const int nchunks = (rcnt + RC - 1) / RC;
        const int nchq    = (nchunks + NSPLIT - 1) / NSPLIT;
        const int cbase   = split * nchq;
        const int ncu     = min(nchunks, cbase + nchq) - cbase;
        const int nslots  = (ncu > 0) ? ncu * kcN : 0;

        if (nslots > 0) {
            // ---- cp.async slice issue (Xi + Xr only) ----
            auto issue_slice = [&](int slot) {
                const int cu    = slot / kcN;
                const int kc    = slot - cu * kcN;
                const int buf   = slot % 3;
                const int r0    = (cbase + cu) * RC;
                const int rn    = min(RC, rcnt - r0);
                #pragma unroll
                for (int it = 0; it < 4; it++) {
                    int idx  = tid + it * 256;
                    int half = idx >> 9;
                    int v    = idx & 511;
                    int row  = v >> 2;
                    int fu   = (v & 3) * 8;
                    int f    = kc * KS + fu;
                    bool ok  = (row < cw) && (f < dfeat);
                    const __nv_bfloat16* base = half ? d_Xil : d_Xih;
                    const __nv_bfloat16* ga = base + (ok ? ((size_t)(in_off + tile_c0 + row) * dfeat + f) : 0);
                    int ssz = ok ? min(16, (dfeat - f) * 2) : 0;
                    uint32_t sa = sb + OFF_XI + (uint32_t)(buf * 2 + half) * XI_HB + (uint32_t)(row * PX + fu * 2);
                    CP_ASYNC16(sa, ga, ssz);
                }
                #pragma unroll
                for (int it = 0; it < 2; it++) {
                    int idx  = tid + it * 256;
                    int half = idx >> 8;
                    int v    = idx & 255;
                    int row  = v >> 2;
                    int fu   = (v & 3) * 8;
                    int f    = kc * KS + fu;
                    bool ok  = (row < rn) && (f < dfeat);
                    const __nv_bfloat16* base = half ? d_Xrl : d_Xrh;
                    const __nv_bfloat16* ga = base + (ok ? ((size_t)(roff + r0 + row) * dfeat + f) : 0);
                    int ssz = ok ? min(16, (dfeat - f) * 2) : 0;
                    uint32_t sa = sb + OFF_XR + (uint32_t)(buf * 2 + half) * XR_HB + (uint32_t)(row * PX + fu * 2);
                    CP_ASYNC16(sa, ga, ssz);
                }
                CP_COMMIT();
            };

            float yacc[8][4], sacc[8][4];
            #pragma unroll
            for (int t = 0; t < 8; t++)
                #pragma unroll
                for (int e = 0; e < 4; e++) { yacc[t][e] = 0.0f; sacc[t][e] = 0.0f; }

            issue_slice(0);
            if (nslots > 1) issue_slice(1);

            for (int slot = 0; slot < nslots; slot++) {
                const int cu  = slot / kcN;
                const int kc  = slot - cu * kcN;
                const int buf = slot % 3;

                if (slot == nslots - 1) { CP_WAIT0(); } else { CP_WAIT1(); }
                __syncthreads();
                if (slot + 2 < nslots) issue_slice(slot + 2);

                // ---- stage 1 MMAs on this K-slice ----
                const uint32_t xiH = sb + OFF_XI + (uint32_t)(buf * 2 + 0) * XI_HB;
                const uint32_t xiL = sb + OFF_XI + (uint32_t)(buf * 2 + 1) * XI_HB;
                const uint32_t xrH = sb + OFF_XR + (uint32_t)(buf * 2 + 0) * XR_HB;
                const uint32_t xrL = sb + OFF_XR + (uint32_t)(buf * 2 + 1) * XR_HB;
                #pragma unroll
                for (int ks = 0; ks < 2; ks++) {
                    uint32_t aH[4], aL[4];
                    const uint32_t aoff = a_row * PX + (uint32_t)ks * 32 + a_cofs;
                    LDSM_X4(aH[0], aH[1], aH[2], aH[3], xiH + aoff);
                    LDSM_X4(aL[0], aL[1], aL[2], aL[3], xiL + aoff);
                    #pragma unroll
                    for (int q = 0; q < 4; q++) {
                        uint32_t bH[4], bL[4];
                        const uint32_t boff = (16u * q + b_rsub) * PX + (uint32_t)ks * 32 + b_cofs;
                        LDSM_X4(bH[0], bH[1], bH[2], bH[3], xrH + boff);
                        LDSM_X4(bL[0], bL[1], bL[2], bL[3], xrL + boff);
                        MMA_BF16(sacc[2 * q],     aH, bH[0], bH[1]);
                        MMA_BF16(sacc[2 * q],     aH, bL[0], bL[1]);
                        MMA_BF16(sacc[2 * q],     aL, bH[0], bH[1]);
                        MMA_BF16(sacc[2 * q + 1], aH, bH[2], bH[3]);
                        MMA_BF16(sacc[2 * q + 1], aH, bL[2], bL[3]);
                        MMA_BF16(sacc[2 * q + 1], aL, bH[2], bH[3]);
                    }
                }

                // ---- end of chunk: stage 2 (PH*AtH + PH*AtL + PL*AtH) ----
                if (kc == kcN - 1) {
                    const int rblk = (roff + (cbase + cu) * RC) >> 6;
                    const uint4* __restrict__ atf = d_AtF + (size_t)rblk * 1024 + lid;
                    #pragma unroll
                    for (int ks = 0; ks < 4; ks++) {
                        const int j0 = 2 * ks, j1 = 2 * ks + 1;
                        float p0 = ipow_f(sacc[j0][0], ek), p1 = ipow_f(sacc[j0][1], ek);
                        float p2 = ipow_f(sacc[j0][2], ek), p3 = ipow_f(sacc[j0][3], ek);
                        float q0 = ipow_f(sacc[j1][0], ek), q1 = ipow_f(sacc[j1][1], ek);
                        float q2 = ipow_f(sacc[j1][2], ek), q3 = ipow_f(sacc[j1][3], ek);
                        float h0 = __bfloat162float(__float2bfloat16(p0));
                        float h1 = __bfloat162float(__float2bfloat16(p1));
                        float h2 = __bfloat162float(__float2bfloat16(p2));
                        float h3 = __bfloat162float(__float2bfloat16(p3));
                        float i0 = __bfloat162float(__float2bfloat16(q0));
                        float i1 = __bfloat162float(__float2bfloat16(q1));
                        float i2 = __bfloat162float(__float2bfloat16(q2));
                        float i3 = __bfloat162float(__float2bfloat16(q3));
                        uint32_t aH[4], aL[4];
                        aH[0] = pack_bf16(h0, h1); aL[0] = pack_bf16(p0 - h0, p1 - h1);
                        aH[1] = pack_bf16(h2, h3); aL[1] = pack_bf16(p2 - h2, p3 - h3);
                        aH[2] = pack_bf16(i0, i1); aL[2] = pack_bf16(q0 - i0, q1 - i1);
                        aH[3] = pack_bf16(i2, i3); aL[3] = pack_bf16(q2 - i2, q3 - i3);
                        #pragma unroll
                        for (int q = 0; q < 4; q++) {
                            uint4 BH = atf[(size_t)((ks * 4 + q) * 2 + 0) * 32];
                            uint4 BL = atf[(size_t)((ks * 4 + q) * 2 + 1) * 32];
                            uint32_t bH[4] = {BH.x, BH.y, BH.z, BH.w};
                            uint32_t bL[4] = {BL.x, BL.y, BL.z, BL.w};
                            MMA_BF16(yacc[2 * q],     aH, bH[0], bH[1]);
                            MMA_BF16(yacc[2 * q],     aH, bL[0], bL[1]);
                            MMA_BF16(yacc[2 * q],     aL, bH[0], bH[1]);
                            MMA_BF16(yacc[2 * q + 1], aH, bH[2], bH[3]);
                            MMA_BF16(yacc[2 * q + 1], aH, bL[2], bL[3]);
                            MMA_BF16(yacc[2 * q + 1], aL, bH[2], bH[3]);
                        }
                    }
                    #pragma unroll
                    for (int t = 0; t < 8; t++)
                        #pragma unroll
                        for (int e = 0; e < 4; e++) sacc[t][e] = 0.0f;
                }
            }

            // ---- epilogue: write split partial (plain stores; unit owns buffer) ----
            const int gg = lid >> 2, t4 = lid & 3;
            const int cA = wrow + gg, cB = cA + 8;
            const int oA = (cA < cw) ? d_in_perm[in_off + tile_c0 + cA] : -1;
            const int oB = (cB < cw) ? d_in_perm[in_off + tile_c0 + cB] : -1;
            float* part = d_part + (size_t)split * NP_MAX * NIN_MAX;
            #pragma unroll
            for (int t = 0; t < 8; t++) {
                int p = 8 * t + 2 * t4;
                if (p < np) {
                    if (oA >= 0 && oA < Nin) part[(size_t)p * NIN_MAX + oA] = yacc[t][0];
                    if (oB >= 0 && oB < Nin) part[(size_t)p * NIN_MAX + oB] = yacc[t][2];
                }
                if (p + 1 < np) {
                    if (oA >= 0 && oA < Nin) part[(size_t)(p + 1) * NIN_MAX + oA] = yacc[t][1];
                    if (oB >= 0 && oB < Nin) part[(size_t)(p + 1) * NIN_MAX + oB] = yacc[t][3];
                }
            }
        }

        // ---- tile completion protocol (ALL units, including empty splits) ----
        __threadfence();                       // make this unit's partials visible
        __syncthreads();
        if (tid == 0) s_done = atomicAdd(&d_tile_done[tile], 1);
        __syncthreads();
        if (s_done == NSPLIT - 1) {
            if (tid == 0) __threadfence();     // acquire other splits' stores
            __syncthreads();
            // fixed-order reduce of this tile's columns -> out
            const int total = np * BC;
            for (int idx = tid; idx < total; idx += 256) {
                const int p = idx >> 7;        // / BC
                const int c = idx & (BC - 1);
                if (c < cw) {
                    const int orig = d_in_perm[in_off + tile_c0 + c];
                    if (orig >= 0 && orig < Nin) {
                        float s = 0.0f;
                        #pragma unroll
                        for (int sp = 0; sp < NSPLIT; sp++)
                            s += d_part[((size_t)sp * NP_MAX + p) * NIN_MAX + orig];
                        out[(size_t)p * Nin + orig] = s;
                    }
                }
            }
            if (tid == 0) d_tile_done[tile] = 0;   // reset for next graph replay
        }
    }
}

// ---------------- launch ----------------
extern "C" void kernel_launch(void* const* d_in, const int* in_sizes, int n_in,
                              void* d_out, int out_size) {
    const float* Alpha    = (const float*)d_in[0];
    const int*   Zr       = (const int*)d_in[1];
    const float* desc_ref = (const float*)d_in[2];
    const int*   Zi       = (const int*)d_in[3];
    const float* desc     = (const float*)d_in[4];
    const int*   expKp    = (const int*)d_in[5];

    int Nref = in_sizes[1];
    int Nin  = in_sizes[3];
    if (Nref > NREF_MAX - MAXG * 64) Nref = NREF_MAX - MAXG * 64;
    if (Nin  > NIN_MAX  - MAXG * 64) Nin  = NIN_MAX  - MAXG * 64;
    int np = in_sizes[0] / Nref;
    if (np > NP_MAX) np = NP_MAX;
    int dfeat = in_sizes[2] / Nref;
    if (dfeat > 256) dfeat = 256;

    cudaFuncSetAttribute(main_kernel, cudaFuncAttributeMaxDynamicSharedMemorySize, SMEM_TOTAL);

    prep_kernel<<<1, 256>>>(Zr, Zi, Nref, Nin);

    const int padRef = Nref + MAXG * 64;
    const int padIn  = Nin  + MAXG * 64;
    const int grows  = padRef + padIn;
    gather_kernel<<<(grows + 3) / 4, 256>>>(Alpha, desc_ref, desc, np, dfeat, Nref, Nin, padRef);

    atfrag_kernel<<<256, 256>>>(np);

    zero_out_kernel<<<256, 256>>>((float*)d_out, (size_t)out_size);

    main_kernel<<<GRID_MAIN, 256, SMEM_TOTAL>>>((float*)d_out, np, dfeat, Nin, expKp);
}

// round 16
// speedup vs baseline: 1.0980x; 1.0980x over previous
#include <cuda_runtime.h>
#include <cuda_bf16.h>
#include <cstdint>
#include <cstddef>

// ---------------- problem maxima: 12800 ref, 25600 in, 256 feat, 64 props ----
#define NREF_MAX 16384
#define NIN_MAX  32768
#define NP_MAX   64
#define MAXG     16
#define BC       128     // input-atom columns per tile
#define RC       64      // ref atoms per chunk
#define KS       64      // feature K-slice per pipeline stage
#define NTILE_MAX 512
#define NSPLIT   4       // ref-chunk split per tile (work units = tiles * NSPLIT)
#define GRID_MAIN 296    // persistent CTAs (148 SMs x 2)

// ---------------- device scratch (static: no allocation) ----------------
__device__ int d_ng, d_nt, d_totref, d_totin;
__device__ int d_wctr;
__device__ int d_gref_off[MAXG], d_gref_cnt[MAXG];
__device__ int d_gin_off[MAXG],  d_gin_cnt[MAXG];
__device__ int d_tile_g[NTILE_MAX], d_tile_c0[NTILE_MAX];
// perm arrays: static zero-init; gap entries never written -> deterministic.
__device__ int d_ref_perm[NREF_MAX], d_in_perm[NIN_MAX];
__device__ __nv_bfloat16 d_Xrh[(size_t)NREF_MAX * 256];
__device__ __nv_bfloat16 d_Xrl[(size_t)NREF_MAX * 256];
__device__ __nv_bfloat16 d_Xih[(size_t)NIN_MAX  * 256];
__device__ __nv_bfloat16 d_Xil[(size_t)NIN_MAX  * 256];
__device__ __nv_bfloat16 d_Ath[(size_t)NP_MAX * NREF_MAX]; // [prop][ref_grouped]
__device__ __nv_bfloat16 d_Atl[(size_t)NP_MAX * NREF_MAX];
// fragment-ready At: [rblk(256)][ks(4)][q(4)][half(2)][lane(32)] x uint4
__device__ uint4 d_AtF[262144];
// d_part: static zero-init; covered entries rewritten every launch.
__device__ float d_part[(size_t)NSPLIT * NP_MAX * NIN_MAX];

// ---------------- helpers ----------------
__device__ __forceinline__ uint32_t smem_u32(const void* p) {
    uint32_t a;
    asm("{ .reg .u64 t; cvta.to.shared.u64 t, %1; cvt.u32.u64 %0, t; }" : "=r"(a) : "l"(p));
    return a;
}
#define LDSM_X4(r0, r1, r2, r3, addr) \
    asm volatile("ldmatrix.sync.aligned.m8n8.x4.shared.b16 {%0,%1,%2,%3}, [%4];" \
        : "=r"(r0), "=r"(r1), "=r"(r2), "=r"(r3) : "r"(addr))
#define MMA_BF16(c, a, b0, b1) \
    asm volatile("mma.sync.aligned.m16n8k16.row.col.f32.bf16.bf16.f32 " \
        "{%0,%1,%2,%3},{%4,%5,%6,%7},{%8,%9},{%0,%1,%2,%3};" \
        : "+f"((c)[0]), "+f"((c)[1]), "+f"((c)[2]), "+f"((c)[3]) \
        : "r"((a)[0]), "r"((a)[1]), "r"((a)[2]), "r"((a)[3]), "r"(b0), "r"(b1))
#define CP_ASYNC16(sa, ga, ssz) \
    asm volatile("cp.async.cg.shared.global [%0], [%1], 16, %2;" \
        :: "r"(sa), "l"(ga), "r"(ssz) : "memory")
#define CP_COMMIT() asm volatile("cp.async.commit_group;" ::: "memory")
#define CP_WAIT0()  asm volatile("cp.async.wait_group 0;" ::: "memory")

__device__ __forceinline__ uint32_t pack_bf16(float lo, float hi) {
    uint32_t d;
    asm("cvt.rn.bf16x2.f32 %0, %1, %2;" : "=r"(d) : "f"(hi), "f"(lo));
    return d;
}
__device__ __forceinline__ float ipow_f(float x, int e) {
    if (e == 2) return x * x;
    if (e == 1) return x;
    float r = 1.0f, b = x; int k = e;
    while (k > 0) { if (k & 1) r *= b; b *= b; k >>= 1; }
    return r;
}

// ---- smem: 2-buffer pipeline, KS=64 slices, pitch 144B (64 bf16 + 16B pad) ----
#define PX      144
#define XI_HB   (128 * PX)                 // 18432 per (buf,half)
#define XR_HB   (64 * PX)                  // 9216
#define OFF_XI  0
#define OFF_XR  (OFF_XI + 4 * XI_HB)       // 73728
#define SMEM_TOTAL (OFF_XR + 4 * XR_HB)    // 110592

// ---------------- prep: dtype-detect Z, histogram, aligned groups, perm ----------
__global__ void prep_kernel(const int* __restrict__ Zr, const int* __restrict__ Zi,
                            int Nref, int Nin) {
    __shared__ int s_h_ref[256], s_h_in[256], s_gmap[256];
    __shared__ int s_flag[2];
    __shared__ int s_lcs[256][MAXG];
    int tid = threadIdx.x;

    if (tid < 2) s_flag[tid] = 1;
    for (int v = tid; v < 256; v += 256) { s_h_ref[v] = 0; s_h_in[v] = 0; s_gmap[v] = -1; }
    __syncthreads();

    for (int i = 1 + 2 * tid; i < Nref; i += 512) if (Zr[i] != 0) { s_flag[0] = 0; break; }
    for (int i = 1 + 2 * tid; i < Nin;  i += 512) if (Zi[i] != 0) { s_flag[1] = 0; break; }
    __syncthreads();
    const int r64 = s_flag[0], i64 = s_flag[1];

    for (int i = tid; i < Nref; i += 256) {
        int v = Zr[r64 ? 2 * i : i];
        if (v >= 1 && v < 256) atomicAdd(&s_h_ref[v], 1);
    }
    for (int i = tid; i < Nin; i += 256) {
        int v = Zi[i64 ? 2 * i : i];
        if (v >= 1 && v < 256) atomicAdd(&s_h_in[v], 1);
    }
    __syncthreads();

    if (tid == 0) {
        int ng = 0, roff = 0, ioff = 0, nt = 0;
        for (int v = 1; v < 256; v++) {
            if (s_h_in[v] > 0 && ng < MAXG) {
                roff = (roff + 63) & ~63; ioff = (ioff + 63) & ~63;
                s_gmap[v] = ng;
                d_gref_off[ng] = roff; d_gref_cnt[ng] = s_h_ref[v];
                d_gin_off[ng]  = ioff; d_gin_cnt[ng]  = s_h_in[v];
                for (int c0 = 0; c0 < s_h_in[v]; c0 += BC)
                    if (nt < NTILE_MAX) { d_tile_g[nt] = ng; d_tile_c0[nt] = c0; nt++; }
                roff += s_h_ref[v]; ioff += s_h_in[v]; ng++;
            }
        }
        d_ng = ng; d_nt = nt; d_totref = roff; d_totin = ioff;
        d_wctr = 0;
    }
    __syncthreads();
    const int ng = d_ng;

    { // counting-sort perm: ref
        int chunk = (Nref + 255) >> 8;
        int i0 = tid * chunk, i1 = min(Nref, i0 + chunk);
        int lc[MAXG];
        #pragma unroll
        for (int g = 0; g < MAXG; g++) lc[g] = 0;
        for (int i = i0; i < i1; i++) {
            int v = Zr[r64 ? 2 * i : i];
            int g = (v >= 1 && v < 256) ? s_gmap[v] : -1;
            if (g >= 0) lc[g]++;
        }
        #pragma unroll
        for (int g = 0; g < MAXG; g++) s_lcs[tid][g] = lc[g];
        __syncthreads();
        if (tid < ng) {
            int acc = d_gref_off[tid];
            for (int t = 0; t < 256; t++) { int x = s_lcs[t][tid]; s_lcs[t][tid] = acc; acc += x; }
        }
        __syncthreads();
        int cur[MAXG];
        #pragma unroll
        for (int g = 0; g < MAXG; g++) cur[g] = s_lcs[tid][g];
        for (int i = i0; i < i1; i++) {
            int v = Zr[r64 ? 2 * i : i];
            int g = (v >= 1 && v < 256) ? s_gmap[v] : -1;
            if (g >= 0) { int p = cur[g]++; if (p < NREF_MAX) d_ref_perm[p] = i; }
        }
        __syncthreads();
    }
    { // counting-sort perm: input
        int chunk = (Nin + 255) >> 8;
        int i0 = tid * chunk, i1 = min(Nin, i0 + chunk);
        int lc[MAXG];
        #pragma unroll
        for (int g = 0; g < MAXG; g++) lc[g] = 0;
        for (int i = i0; i < i1; i++) {
            int v = Zi[i64 ? 2 * i : i];
            int g = (v >= 1 && v < 256) ? s_gmap[v] : -1;
            if (g >= 0) lc[g]++;
        }
        #pragma unroll
        for (int g = 0; g < MAXG; g++) s_lcs[tid][g] = lc[g];
        __syncthreads();
        if (tid < ng) {
            int acc = d_gin_off[tid];
            for (int t = 0; t < 256; t++) { int x = s_lcs[t][tid]; s_lcs[t][tid] = acc; acc += x; }
        }
        __syncthreads();
        int cur[MAXG];
        #pragma unroll
        for (int g = 0; g < MAXG; g++) cur[g] = s_lcs[tid][g];
        for (int i = i0; i < i1; i++) {
            int v = Zi[i64 ? 2 * i : i];
            int g = (v >= 1 && v < 256) ? s_gmap[v] : -1;
            if (g >= 0) { int p = cur[g]++; if (p < NIN_MAX) d_in_perm[p] = i; }
        }
    }
}

// ---------------- gather + bf16 hi/lo split (4 rows/block, vectorized) ----------
__global__ void gather_kernel(const float* __restrict__ Alpha,
                              const float* __restrict__ desc_ref,
                              const float* __restrict__ desc,
                              int np, int dfeat, int Nref, int Nin, int padRef) {
    const int tid = threadIdx.x;
    const int rl  = tid >> 6;
    const int ln  = tid & 63;
    const int row = blockIdx.x * 4 + rl;
    const bool vec = ((dfeat & 3) == 0);

    if (row < padRef) {
        if (row < d_totref) {
            int src = d_ref_perm[row];
            if (vec) {
                for (int k4 = ln * 4; k4 < dfeat; k4 += 256) {
                    float4 x = *(const float4*)&desc_ref[(size_t)src * dfeat + k4];
                    float h0 = __bfloat162float(__float2bfloat16(x.x));
                    float h1 = __bfloat162float(__float2bfloat16(x.y));
                    float h2 = __bfloat162float(__float2bfloat16(x.z));
                    float h3 = __bfloat162float(__float2bfloat16(x.w));
                    uint2 hv, lv;
                    hv.x = pack_bf16(h0, h1); hv.y = pack_bf16(h2, h3);
                    lv.x = pack_bf16(x.x - h0, x.y - h1); lv.y = pack_bf16(x.z - h2, x.w - h3);
                    *(uint2*)&d_Xrh[(size_t)row * dfeat + k4] = hv;
                    *(uint2*)&d_Xrl[(size_t)row * dfeat + k4] = lv;
                }
            } else {
                for (int k = ln; k < dfeat; k += 64) {
                    float x = desc_ref[(size_t)src * dfeat + k];
                    __nv_bfloat16 h = __float2bfloat16(x);
                    d_Xrh[(size_t)row * dfeat + k] = h;
                    d_Xrl[(size_t)row * dfeat + k] = __float2bfloat16(x - __bfloat162float(h));
                }
            }
            float a = (ln < np) ? Alpha[(size_t)ln * Nref + src] : 0.0f;
            __nv_bfloat16 h = __float2bfloat16(a);
            d_Ath[(size_t)ln * NREF_MAX + row] = h;
            d_Atl[(size_t)ln * NREF_MAX + row] = __float2bfloat16(a - __bfloat162float(h));
        }
    } else {
        int ir = row - padRef;
        if (ir < d_totin) {
            int src = d_in_perm[ir];
            if (vec) {
                for (int k4 = ln * 4; k4 < dfeat; k4 += 256) {
                    float4 x = *(const float4*)&desc[(size_t)src * dfeat + k4];
                    float h0 = __bfloat162float(__float2bfloat16(x.x));
                    float h1 = __bfloat162float(__float2bfloat16(x.y));
                    float h2 = __bfloat162float(__float2bfloat16(x.z));
                    float h3 = __bfloat162float(__float2bfloat16(x.w));
                    uint2 hv, lv;
                    hv.x = pack_bf16(h0, h1); hv.y = pack_bf16(h2, h3);
                    lv.x = pack_bf16(x.x - h0, x.y - h1); lv.y = pack_bf16(x.z - h2, x.w - h3);
                    *(uint2*)&d_Xih[(size_t)ir * dfeat + k4] = hv;
                    *(uint2*)&d_Xil[(size_t)ir * dfeat + k4] = lv;
                }
            } else {
                for (int k = ln; k < dfeat; k += 64) {
                    float x = desc[(size_t)src * dfeat + k];
                    __nv_bfloat16 h = __float2bfloat16(x);
                    d_Xih[(size_t)ir * dfeat + k] = h;
                    d_Xil[(size_t)ir * dfeat + k] = __float2bfloat16(x - __bfloat162float(h));
                }
            }
        }
    }
}

// ---------------- build fragment-ready At (coalesced via smem tile) -------------
__global__ void atfrag_kernel(int np) {
    __shared__ __align__(16) unsigned short s_at[2][64][72];
    __shared__ int s_off[MAXG], s_cnt[MAXG], s_ng;
    const int tid  = threadIdx.x;
    const int rblk = blockIdx.x;

    if (tid == 0) s_ng = d_ng;
    if (tid < MAXG) { s_off[tid] = d_gref_off[tid]; s_cnt[tid] = d_gref_cnt[tid]; }

    #pragma unroll
    for (int h = 0; h < 2; h++) {
        const __nv_bfloat16* src = h ? d_Atl : d_Ath;
        #pragma unroll
        for (int it = 0; it < 2; it++) {
            int i   = tid + it * 256;
            int row = i >> 3;
            int c   = i & 7;
            uint4 v = *(const uint4*)(src + (size_t)row * NREF_MAX + rblk * 64 + c * 8);
            *(uint4*)&s_at[h][row][c * 8] = v;
        }
    }
    __syncthreads();

    const int ng = s_ng;
    const int base_ref = rblk * 64;

    #pragma unroll
    for (int o = 0; o < 4; o++) {
        int local = tid + o * 256;
        int lid  = local & 31;
        int rest = local >> 5;
        int half = rest & 1; rest >>= 1;
        int q    = rest & 3; rest >>= 2;
        int ks   = rest & 3;
        uint32_t regs[4];
        #pragma unroll
        for (int r = 0; r < 4; r++) {
            int prop = 16 * q + 8 * (r >> 1) + (lid >> 2);
            int refl = ks * 16 + 8 * (r & 1) + 2 * (lid & 3);
            uint32_t w = *(const uint32_t*)&s_at[half][prop][refl];
            #pragma unroll
            for (int e = 0; e < 2; e++) {
                int rr = base_ref + refl + e;
                bool ing = false;
                for (int g = 0; g < ng; g++)
                    if (rr >= s_off[g] && rr < s_off[g] + s_cnt[g]) { ing = true; break; }
                if (!ing) w &= (e == 0) ? 0xFFFF0000u : 0x0000FFFFu;
            }
            regs[r] = w;
        }
        d_AtF[(size_t)rblk * 1024 + local] = make_uint4(regs[0], regs[1], regs[2], regs[3]);
    }
}

// ---------------- main: persistent, work-stealing, 2-buffer KS=64 pipeline -----
__global__ __launch_bounds__(256, 2)
void main_kernel(int np, int dfeat, int Nin, const int* __restrict__ expKp) {
    extern __shared__ char smem[];
    __shared__ int s_unit;
    const uint32_t sb = smem_u32(smem);
    const int tid = threadIdx.x;
    const int wid = tid >> 5;
    const int lid = tid & 31;

    int ek = expKp[0];
    if (ek < 1 || ek > 64) {
        float f = __int_as_float(ek); int t = (int)f;
        ek = (t >= 1 && t <= 64) ? t : 2;
    }

    const int kcN = (dfeat + KS - 1) / KS;    // 4 for dfeat=256
    const int wrow = wid * 16;

    const uint32_t a_row  = (uint32_t)(wrow + (lid & 15));
    const uint32_t a_cofs = (uint32_t)((lid >> 4) * 16);
    const uint32_t b_rsub = (uint32_t)(8 * (lid >> 4) + (lid & 7));
    const uint32_t b_cofs = (uint32_t)(((lid >> 3) & 1) * 16);

    for (;;) {
        __syncthreads();                      // unit boundary: buffers quiesced
        if (tid == 0) s_unit = atomicAdd(&d_wctr, 1);
        __syncthreads();
        const int u = s_unit;
        const int nunits = d_nt * NSPLIT;
        if (u >= nunits) break;

        const int tile  = u >> 2;
        const int split = u & 3;
        const int g       = d_tile_g[tile];
        const int tile_c0 = d_tile_c0[tile];
        const int in_off  = d_gin_off[g];
        const int cw      = min(BC, d_gin_cnt[g] - tile_c0);
        const int roff    = d_gref_off[g];
        const int rcnt    = d_gref_cnt[g];
        const int nchunks = (rcnt + RC - 1) / RC;
        const int nchq    = (nchunks + NSPLIT - 1) / NSPLIT;
        const int cbase   = split * nchq;
        const int ncu     = min(nchunks, cbase + nchq) - cbase;
        if (ncu <= 0) continue;
        const int nslots  = ncu * kcN;

        // ---- cp.async slice issue: KS=64 feats of Xi tile + Xr chunk ----
        auto issue_slice = [&](int slot) {
            const int cu    = slot / kcN;
            const int kc    = slot - cu * kcN;
            const int buf   = slot & 1;
            const int r0    = (cbase + cu) * RC;
            const int rn    = min(RC, rcnt - r0);
            // Xi: 128 rows x 64 feats x 2 halves = 2048 x 16B
            #pragma unroll
            for (int it = 0; it < 8; it++) {
                int idx  = tid + it * 256;
                int half = idx >> 10;
                int v    = idx & 1023;
                int row  = v >> 3;
                int fu   = (v & 7) * 8;
                int f    = kc * KS + fu;
                bool ok  = (row < cw) && (f < dfeat);
                const __nv_bfloat16* base = half ? d_Xil : d_Xih;
                const __nv_bfloat16* ga = base + (ok ? ((size_t)(in_off + tile_c0 + row) * dfeat + f) : 0);
                int ssz = ok ? min(16, (dfeat - f) * 2) : 0;
                uint32_t sa = sb + OFF_XI + (uint32_t)(buf * 2 + half) * XI_HB + (uint32_t)(row * PX + fu * 2);
                CP_ASYNC16(sa, ga, ssz);
            }
            // Xr: 64 rows x 64 feats x 2 halves = 1024 x 16B
            #pragma unroll
            for (int it = 0; it < 4; it++) {
                int idx  = tid + it * 256;
                int half = idx >> 9;
                int v    = idx & 511;
                int row  = v >> 3;
                int fu   = (v & 7) * 8;
                int f    = kc * KS + fu;
                bool ok  = (row < rn) && (f < dfeat);
                const __nv_bfloat16* base = half ? d_Xrl : d_Xrh;
                const __nv_bfloat16* ga = base + (ok ? ((size_t)(roff + r0 + row) * dfeat + f) : 0);
                int ssz = ok ? min(16, (dfeat - f) * 2) : 0;
                uint32_t sa = sb + OFF_XR + (uint32_t)(buf * 2 + half) * XR_HB + (uint32_t)(row * PX + fu * 2);
                CP_ASYNC16(sa, ga, ssz);
            }
            CP_COMMIT();
        };

        float yacc[8][4], sacc[8][4];
        #pragma unroll
        for (int t = 0; t < 8; t++)
            #pragma unroll
            for (int e = 0; e < 4; e++) { yacc[t][e] = 0.0f; sacc[t][e] = 0.0f; }

        if (nslots > 0) issue_slice(0);

        for (int slot = 0; slot < nslots; slot++) {
            const int cu  = slot / kcN;
            const int kc  = slot - cu * kcN;
            const int buf = slot & 1;

            CP_WAIT0();            // slot's group is the only outstanding one
            __syncthreads();       // all warps past consume(slot-1); data visible
            if (slot + 1 < nslots) issue_slice(slot + 1);  // into slot-1's buffer: safe

            // ---- stage 1 MMAs: 4 x k16 sub-slices ----
            const uint32_t xiH = sb + OFF_XI + (uint32_t)(buf * 2 + 0) * XI_HB;
            const uint32_t xiL = sb + OFF_XI + (uint32_t)(buf * 2 + 1) * XI_HB;
            const uint32_t xrH = sb + OFF_XR + (uint32_t)(buf * 2 + 0) * XR_HB;
            const uint32_t xrL = sb + OFF_XR + (uint32_t)(buf * 2 + 1) * XR_HB;
            #pragma unroll
            for (int ks = 0; ks < 4; ks++) {
                uint32_t aH[4], aL[4];
                const uint32_t aoff = a_row * PX + (uint32_t)ks * 32 + a_cofs;
                LDSM_X4(aH[0], aH[1], aH[2], aH[3], xiH + aoff);
                LDSM_X4(aL[0], aL[1], aL[2], aL[3], xiL + aoff);
                #pragma unroll
                for (int q = 0; q < 4; q++) {
                    uint32_t bH[4], bL[4];
                    const uint32_t boff = (16u * q + b_rsub) * PX + (uint32_t)ks * 32 + b_cofs;
                    LDSM_X4(bH[0], bH[1], bH[2], bH[3], xrH + boff);
                    LDSM_X4(bL[0], bL[1], bL[2], bL[3], xrL + boff);
                    MMA_BF16(sacc[2 * q],     aH, bH[0], bH[1]);
                    MMA_BF16(sacc[2 * q],     aH, bL[0], bL[1]);
                    MMA_BF16(sacc[2 * q],     aL, bH[0], bH[1]);
                    MMA_BF16(sacc[2 * q + 1], aH, bH[2], bH[3]);
                    MMA_BF16(sacc[2 * q + 1], aH, bL[2], bL[3]);
                    MMA_BF16(sacc[2 * q + 1], aL, bH[2], bH[3]);
                }
            }

            // ---- end of chunk: stage 2 (PH*AtH + PH*AtL + PL*AtH) ----
            if (kc == kcN - 1) {
                const int rblk = (roff + (cbase + cu) * RC) >> 6;
                const uint4* __restrict__ atf = d_AtF + (size_t)rblk * 1024 + lid;
                #pragma unroll
                for (int ks = 0; ks < 4; ks++) {
                    const int j0 = 2 * ks, j1 = 2 * ks + 1;
                    float p0 = ipow_f(sacc[j0][0], ek), p1 = ipow_f(sacc[j0][1], ek);
                    float p2 = ipow_f(sacc[j0][2], ek), p3 = ipow_f(sacc[j0][3], ek);
                    float q0 = ipow_f(sacc[j1][0], ek), q1 = ipow_f(sacc[j1][1], ek);
                    float q2 = ipow_f(sacc[j1][2], ek), q3 = ipow_f(sacc[j1][3], ek);
                    float h0 = __bfloat162float(__float2bfloat16(p0));
                    float h1 = __bfloat162float(__float2bfloat16(p1));
                    float h2 = __bfloat162float(__float2bfloat16(p2));
                    float h3 = __bfloat162float(__float2bfloat16(p3));
                    float i0 = __bfloat162float(__float2bfloat16(q0));
                    float i1 = __bfloat162float(__float2bfloat16(q1));
                    float i2 = __bfloat162float(__float2bfloat16(q2));
                    float i3 = __bfloat162float(__float2bfloat16(q3));
                    uint32_t aH[4], aL[4];
                    aH[0] = pack_bf16(h0, h1); aL[0] = pack_bf16(p0 - h0, p1 - h1);
                    aH[1] = pack_bf16(h2, h3); aL[1] = pack_bf16(p2 - h2, p3 - h3);
                    aH[2] = pack_bf16(i0, i1); aL[2] = pack_bf16(q0 - i0, q1 - i1);
                    aH[3] = pack_bf16(i2, i3); aL[3] = pack_bf16(q2 - i2, q3 - i3);
                    #pragma unroll
                    for (int q = 0; q < 4; q++) {
                        uint4 BH = atf[(size_t)((ks * 4 + q) * 2 + 0) * 32];
                        uint4 BL = atf[(size_t)((ks * 4 + q) * 2 + 1) * 32];
                        uint32_t bH[4] = {BH.x, BH.y, BH.z, BH.w};
                        uint32_t bL[4] = {BL.x, BL.y, BL.z, BL.w};
                        MMA_BF16(yacc[2 * q],     aH, bH[0], bH[1]);
                        MMA_BF16(yacc[2 * q],     aH, bL[0], bL[1]);
                        MMA_BF16(yacc[2 * q],     aL, bH[0], bH[1]);
                        MMA_BF16(yacc[2 * q + 1], aH, bH[2], bH[3]);
                        MMA_BF16(yacc[2 * q + 1], aH, bL[2], bL[3]);
                        MMA_BF16(yacc[2 * q + 1], aL, bH[2], bH[3]);
                    }
                }
                #pragma unroll
                for (int t = 0; t < 8; t++)
                    #pragma unroll
                    for (int e = 0; e < 4; e++) sacc[t][e] = 0.0f;
            }
        }

        // ---- epilogue: write split partial (plain stores; unit owns its buffer) ----
        const int gg = lid >> 2, t4 = lid & 3;
        const int cA = wrow + gg, cB = cA + 8;
        const int oA = (cA < cw) ? d_in_perm[in_off + tile_c0 + cA] : -1;
        const int oB = (cB < cw) ? d_in_perm[in_off + tile_c0 + cB] : -1;
        float* part = d_part + (size_t)split * NP_MAX * NIN_MAX;
        #pragma unroll
        for (int t = 0; t < 8; t++) {
            int p = 8 * t + 2 * t4;
            if (p < np) {
                if (oA >= 0 && oA < Nin) part[(size_t)p * NIN_MAX + oA] = yacc[t][0];
                if (oB >= 0 && oB < Nin) part[(size_t)p * NIN_MAX + oB] = yacc[t][2];
            }
            if (p + 1 < np) {
                if (oA >= 0 && oA < Nin) part[(size_t)(p + 1) * NIN_MAX + oA] = yacc[t][1];
                if (oB >= 0 && oB < Nin) part[(size_t)(p + 1) * NIN_MAX + oB] = yacc[t][3];
            }
        }
    }
}

// ---------------- fixed-order reduction of split partials (vectorized) ----------
__global__ void reduce_kernel(float* __restrict__ out, int np, int Nin) {
    if ((Nin & 3) == 0) {
        const int nq = Nin >> 2;
        size_t n4 = (size_t)np * nq;
        for (size_t idx = (size_t)blockIdx.x * blockDim.x + threadIdx.x; idx < n4;
             idx += (size_t)gridDim.x * blockDim.x) {
            int p  = (int)(idx / nq);
            int i4 = (int)(idx - (size_t)p * nq);
            float4 s = make_float4(0.f, 0.f, 0.f, 0.f);
            #pragma unroll
            for (int sp = 0; sp < NSPLIT; sp++) {
                const float4 v = *(const float4*)&d_part[((size_t)sp * NP_MAX + p) * NIN_MAX + 4 * i4];
                s.x += v.x; s.y += v.y; s.z += v.z; s.w += v.w;
            }
            *(float4*)&out[(size_t)p * Nin + 4 * i4] = s;
        }
    } else {
        size_t n = (size_t)np * Nin;
        for (size_t idx = (size_t)blockIdx.x * blockDim.x + threadIdx.x; idx < n;
             idx += (size_t)gridDim.x * blockDim.x) {
            int p = (int)(idx / Nin);
            int i = (int)(idx - (size_t)p * Nin);
            float s = 0.0f;
            #pragma unroll
            for (int sp = 0; sp < NSPLIT; sp++)
                s += d_part[((size_t)sp * NP_MAX + p) * NIN_MAX + i];
            out[idx] = s;
        }
    }
}

// ---------------- launch ----------------
extern "C" void kernel_launch(void* const* d_in, const int* in_sizes, int n_in,
                              void* d_out, int out_size) {
    const float* Alpha    = (const float*)d_in[0];
    const int*   Zr       = (const int*)d_in[1];
    const float* desc_ref = (const float*)d_in[2];
    const int*   Zi       = (const int*)d_in[3];
    const float* desc     = (const float*)d_in[4];
    const int*   expKp    = (const int*)d_in[5];

    int Nref = in_sizes[1];
    int Nin  = in_sizes[3];
    if (Nref > NREF_MAX - MAXG * 64) Nref = NREF_MAX - MAXG * 64;
    if (Nin  > NIN_MAX  - MAXG * 64) Nin  = NIN_MAX  - MAXG * 64;
    int np = in_sizes[0] / Nref;
    if (np > NP_MAX) np = NP_MAX;
    int dfeat = in_sizes[2] / Nref;
    if (dfeat > 256) dfeat = 256;

    cudaFuncSetAttribute(main_kernel, cudaFuncAttributeMaxDynamicSharedMemorySize, SMEM_TOTAL);

    prep_kernel<<<1, 256>>>(Zr, Zi, Nref, Nin);

    const int padRef = Nref + MAXG * 64;
    const int padIn  = Nin  + MAXG * 64;
    const int grows  = padRef + padIn;
    gather_kernel<<<(grows + 3) / 4, 256>>>(Alpha, desc_ref, desc, np, dfeat, Nref, Nin, padRef);

    atfrag_kernel<<<256, 256>>>(np);

    main_kernel<<<GRID_MAIN, 256, SMEM_TOTAL>>>(np, dfeat, Nin, expKp);

    reduce_kernel<<<512, 256>>>((float*)d_out, np, Nin);
}